// round 3
// baseline (speedup 1.0000x reference)
#include <cuda_runtime.h>
#include <math.h>

#define NCH 256
#define TW 16
#define TH 4
#define OCT 64
#define CB 16
#define WPAD 68   // padded oc dim: float4-aligned reads, low conflict

// Scratch (static device globals; allocation is forbidden)
__device__ float g_buf0[8u*256u*64u*64u];   // 33.5 MB
__device__ float g_buf1[8u*256u*64u*64u];   // 33.5 MB
__device__ float g_head[8u*720u*64u*64u];   // 94.4 MB (max head output, level 0 cls)

// ---------------------------------------------------------------------------
// 3x3 SAME conv, C_in = 256 fixed, OC generic, optional ReLU.
// Block: 256 threads computes [64 oc x 64 px] tile (16x4 spatial).
// Thread: 4 oc x 4 px register tile. Smem chunking over input channels (16).
// Accuracy: per-input-channel 9-tap partial sums folded into the master
// accumulator with a Kahan (compensated) step -> error ~2e-7 instead of
// ~3e-6 for a straight 2304-term chain. Needed: class_id = argmax over 80
// logits flips on ~1e-6 ties vs the XLA reference.
// ---------------------------------------------------------------------------
__global__ __launch_bounds__(256) void conv3x3_k(
    const float* __restrict__ in, const float* __restrict__ wt,
    const float* __restrict__ bias, float* __restrict__ out,
    int OC, int H, int W, int tilesX, int relu)
{
    __shared__ float s_in[CB][TH+2][TW+2];
    __shared__ float s_w[CB*9*WPAD];

    const int t   = threadIdx.x;
    const int tX  = blockIdx.x % tilesX;
    const int tY  = blockIdx.x / tilesX;
    const int oc0 = blockIdx.y * OCT;
    const int b   = blockIdx.z;
    const int og  = t & 15;        // oc group: handles oc0 + og*4 .. +3
    const int pg  = t >> 4;        // pixel group: 4 consecutive x at fixed y
    const int px  = (pg & 3) << 2;
    const int py  = pg >> 2;
    const int gx0 = tX * TW, gy0 = tY * TH;

    float acc[4][4];   // master accumulators
    float cmp[4][4];   // Kahan compensation terms
    #pragma unroll
    for (int j = 0; j < 4; j++)
        #pragma unroll
        for (int i = 0; i < 4; i++) { acc[j][i] = 0.f; cmp[j][i] = 0.f; }

    const float* inb = in + (size_t)b * NCH * H * W;

    for (int cb = 0; cb < NCH; cb += CB) {
        __syncthreads();
        // load input tile (with halo, zero-padded)
        #pragma unroll 2
        for (int i = t; i < CB*(TH+2)*(TW+2); i += 256) {
            int ci  = i / ((TH+2)*(TW+2));
            int rem = i - ci*((TH+2)*(TW+2));
            int r   = rem / (TW+2);
            int c   = rem - r*(TW+2);
            int gy  = gy0 + r - 1;
            int gx  = gx0 + c - 1;
            float v = 0.f;
            if ((unsigned)gy < (unsigned)H && (unsigned)gx < (unsigned)W)
                v = inb[((size_t)(cb+ci)*H + gy)*W + gx];
            s_in[ci][r][c] = v;
        }
        // load weight slice: s_w[(ci*9+tap)*WPAD + oc]
        #pragma unroll 4
        for (int i = t; i < OCT*CB*9; i += 256) {
            int oc = i / (CB*9);
            int j  = i - oc*(CB*9);     // j = ci*9 + tap  (global-coalesced per oc)
            float v = 0.f;
            int goc = oc0 + oc;
            if (goc < OC) v = wt[(size_t)goc*(NCH*9) + (size_t)cb*9 + j];
            s_w[j*WPAD + oc] = v;
        }
        __syncthreads();

        #pragma unroll
        for (int ci = 0; ci < CB; ci++) {
            // per-channel 9-tap partials
            float tt[4][4];
            #pragma unroll
            for (int j = 0; j < 4; j++)
                #pragma unroll
                for (int i = 0; i < 4; i++) tt[j][i] = 0.f;

            #pragma unroll
            for (int ky = 0; ky < 3; ky++) {
                const float* irow = &s_in[ci][py+ky][px];
                float i0 = irow[0], i1 = irow[1], i2 = irow[2];
                float i3 = irow[3], i4 = irow[4], i5 = irow[5];
                #pragma unroll
                for (int kx = 0; kx < 3; kx++) {
                    const float4 wv = *(const float4*)&s_w[(ci*9 + ky*3 + kx)*WPAD + (og<<2)];
                    float a0 = (kx==0)?i0:((kx==1)?i1:i2);
                    float a1 = (kx==0)?i1:((kx==1)?i2:i3);
                    float a2 = (kx==0)?i2:((kx==1)?i3:i4);
                    float a3 = (kx==0)?i3:((kx==1)?i4:i5);
                    tt[0][0] += wv.x*a0; tt[0][1] += wv.x*a1; tt[0][2] += wv.x*a2; tt[0][3] += wv.x*a3;
                    tt[1][0] += wv.y*a0; tt[1][1] += wv.y*a1; tt[1][2] += wv.y*a2; tt[1][3] += wv.y*a3;
                    tt[2][0] += wv.z*a0; tt[2][1] += wv.z*a1; tt[2][2] += wv.z*a2; tt[2][3] += wv.z*a3;
                    tt[3][0] += wv.w*a0; tt[3][1] += wv.w*a1; tt[3][2] += wv.w*a2; tt[3][3] += wv.w*a3;
                }
            }
            // Kahan fold of tt into acc
            #pragma unroll
            for (int j = 0; j < 4; j++) {
                #pragma unroll
                for (int i = 0; i < 4; i++) {
                    float y = tt[j][i] - cmp[j][i];
                    float s = acc[j][i] + y;
                    cmp[j][i] = (s - acc[j][i]) - y;
                    acc[j][i] = s;
                }
            }
        }
    }

    int gy = gy0 + py;
    if (gy >= H) return;
    #pragma unroll
    for (int j = 0; j < 4; j++) {
        int goc = oc0 + og*4 + j;
        if (goc >= OC) continue;
        float bv = bias[goc];
        #pragma unroll
        for (int i = 0; i < 4; i++) {
            int gx = gx0 + px + i;
            if (gx >= W) continue;
            float v = (acc[j][i] - cmp[j][i]) + bv;
            if (relu) v = fmaxf(v, 0.f);
            out[((size_t)b*OC + goc)*H*W + (size_t)gy*W + gx] = v;
        }
    }
}

// ---------------------------------------------------------------------------
// cls epilogue: head [B,720,H,W] (channel = a*80 + k) -> scores + class_id.
// argmax/max on logits == argmax/max on sigmoid (monotone); sigmoid at end.
// ---------------------------------------------------------------------------
__global__ void cls_reduce_k(const float* __restrict__ head,
                             float* __restrict__ scores, float* __restrict__ cls_id,
                             int H, int W, int Aoff, int Atot, int total)
{
    int idx = blockIdx.x * blockDim.x + threadIdx.x;
    if (idx >= total) return;
    int HW  = H * W;
    int pos = idx % HW;
    int tmp = idx / HW;
    int a   = tmp % 9;
    int b   = tmp / 9;
    const float* p = head + ((size_t)b*720 + (size_t)a*80) * HW + pos;
    float best = p[0];
    int   bi   = 0;
    #pragma unroll 4
    for (int k = 1; k < 80; k++) {
        float v = p[(size_t)k * HW];
        if (v > best) { best = v; bi = k; }
    }
    size_t o = (size_t)b*Atot + Aoff + (size_t)pos*9 + a;
    scores[o] = 1.f / (1.f + expf(-best));
    cls_id[o] = (float)bi;
}

// ---------------------------------------------------------------------------
// reg epilogue: head [B,36,H,W] (channel = a*4 + j) -> decoded boxes.
// Anchors computed analytically.
// ---------------------------------------------------------------------------
__global__ void reg_decode_k(const float* __restrict__ head, float* __restrict__ boxes,
                             int H, int W, int stride, int Aoff, int Atot, int total)
{
    int idx = blockIdx.x * blockDim.x + threadIdx.x;
    if (idx >= total) return;
    int HW  = H * W;
    int pos = idx % HW;
    int tmp = idx / HW;
    int a   = tmp % 9;
    int b   = tmp / 9;
    int x   = pos % W, y = pos / W;

    const float* p = head + ((size_t)b*36 + (size_t)a*4) * HW + pos;
    float d0 = p[0], d1 = p[HW], d2 = p[2*(size_t)HW], d3 = p[3*(size_t)HW];

    float s     = (float)stride;
    int   ridx  = a / 3, sidx = a - ridx*3;
    float ratio = (ridx == 0) ? 0.5f : ((ridx == 1) ? 1.f : 2.f);
    float scale = (sidx == 0) ? 1.f : ((sidx == 1) ? 1.2599210498948732f : 1.5874010519681994f);
    float w0 = 4.f * s * scale;
    float aw = w0 * rsqrtf(ratio);
    float ah = aw * ratio;
    float cx = (x + 0.5f) * s;
    float cy = (y + 0.5f) * s;

    float pcx = cx + d0 * 0.1f * aw;
    float pcy = cy + d1 * 0.1f * ah;
    float pw  = expf(d2 * 0.2f) * aw;
    float ph  = expf(d3 * 0.2f) * ah;

    float4 out4 = make_float4(pcx - 0.5f*pw, pcy - 0.5f*ph, pcx + 0.5f*pw, pcy + 0.5f*ph);
    size_t o = ((size_t)b*Atot + Aoff + (size_t)pos*9 + a);
    *(float4*)&boxes[o*4] = out4;
}

// ---------------------------------------------------------------------------
extern "C" void kernel_launch(void* const* d_in, const int* in_sizes, int n_in,
                              void* d_out, int out_size)
{
    static const int HS[5] = {64, 32, 16, 8, 4};
    static const int SS[5] = {8, 16, 32, 64, 128};

    const float* feat[5];
    const float *cw[5], *cbv[5], *rw[5], *rbv[5];
    for (int l = 0; l < 5; l++) feat[l] = (const float*)d_in[l];
    for (int i = 0; i < 5; i++) {
        cw[i]  = (const float*)d_in[5  + 2*i];
        cbv[i] = (const float*)d_in[6  + 2*i];
        rw[i]  = (const float*)d_in[15 + 2*i];
        rbv[i] = (const float*)d_in[16 + 2*i];
    }
    int B = in_sizes[0] / (256 * 64 * 64);

    float *buf0, *buf1, *headb;
    cudaGetSymbolAddress((void**)&buf0,  g_buf0);
    cudaGetSymbolAddress((void**)&buf1,  g_buf1);
    cudaGetSymbolAddress((void**)&headb, g_head);
    float* bufs[2] = {buf0, buf1};

    int Aoff[5], Atot = 0;
    for (int l = 0; l < 5; l++) { Aoff[l] = Atot; Atot += HS[l]*HS[l]*9; }

    float* out        = (float*)d_out;
    float* out_scores = out;
    float* out_cls    = out + (size_t)B * Atot;
    float* out_boxes  = out + (size_t)2 * B * Atot;

    for (int l = 0; l < 5; l++) {
        int H = HS[l], W = HS[l];
        int tilesX = (W + TW - 1) / TW;
        int tilesY = (H + TH - 1) / TH;
        dim3 grid(tilesX * tilesY, 4, B);                       // 256 oc / 64
        dim3 gridCls(tilesX * tilesY, (720 + OCT - 1) / OCT, B);
        dim3 gridReg(tilesX * tilesY, 1, B);                    // 36 oc
        int total = B * 9 * H * W;
        int rblk  = (total + 255) / 256;

        // --- cls tower ---
        const float* x = feat[l];
        for (int i = 0; i < 4; i++) {
            conv3x3_k<<<grid, 256>>>(x, cw[i], cbv[i], bufs[i & 1], 256, H, W, tilesX, 1);
            x = bufs[i & 1];
        }
        conv3x3_k<<<gridCls, 256>>>(x, cw[4], cbv[4], headb, 720, H, W, tilesX, 0);
        cls_reduce_k<<<rblk, 256>>>(headb, out_scores, out_cls, H, W, Aoff[l], Atot, total);

        // --- reg tower ---
        x = feat[l];
        for (int i = 0; i < 4; i++) {
            conv3x3_k<<<grid, 256>>>(x, rw[i], rbv[i], bufs[i & 1], 256, H, W, tilesX, 1);
            x = bufs[i & 1];
        }
        conv3x3_k<<<gridReg, 256>>>(x, rw[4], rbv[4], headb, 36, H, W, tilesX, 0);
        reg_decode_k<<<rblk, 256>>>(headb, out_boxes, H, W, SS[l], Aoff[l], Atot, total);
    }
    (void)n_in; (void)out_size;
}

// round 4
// speedup vs baseline: 1.0014x; 1.0014x over previous
#include <cuda_runtime.h>
#include <math.h>

#define NCH 256
#define TW 16
#define TH 4
#define OCT 64
#define CB 16
#define WPAD 68   // padded oc dim: float4-aligned reads, low conflict

// Scratch (static device globals; allocation is forbidden)
__device__ float g_buf0[8u*256u*64u*64u];   // 33.5 MB
__device__ float g_buf1[8u*256u*64u*64u];   // 33.5 MB
__device__ float g_head[8u*720u*64u*64u];   // 94.4 MB (max head output, level 0 cls)

// ---------------------------------------------------------------------------
// 3x3 SAME conv, C_in = 256 fixed, OC generic, optional ReLU.
// Block: 256 threads computes [64 oc x 64 px] tile (16x4 spatial).
// Thread: 4 oc x 4 px register tile. Smem chunking over input channels (16).
// Accuracy: per-input-channel 9-tap partial sums folded into the master
// accumulator with a Kahan (compensated) step -> error ~2e-7 instead of
// ~3e-6 for a straight 2304-term chain. Needed: class_id = argmax over 80
// logits flips on ~1e-6 ties vs the XLA reference.
// ---------------------------------------------------------------------------
__global__ __launch_bounds__(256) void conv3x3_k(
    const float* __restrict__ in, const float* __restrict__ wt,
    const float* __restrict__ bias, float* __restrict__ out,
    int OC, int H, int W, int tilesX, int relu)
{
    __shared__ float s_in[CB][TH+2][TW+2];
    __shared__ float s_w[CB*9*WPAD];

    const int t   = threadIdx.x;
    const int tX  = blockIdx.x % tilesX;
    const int tY  = blockIdx.x / tilesX;
    const int oc0 = blockIdx.y * OCT;
    const int b   = blockIdx.z;
    const int og  = t & 15;        // oc group: handles oc0 + og*4 .. +3
    const int pg  = t >> 4;        // pixel group: 4 consecutive x at fixed y
    const int px  = (pg & 3) << 2;
    const int py  = pg >> 2;
    const int gx0 = tX * TW, gy0 = tY * TH;

    float acc[4][4];   // master accumulators
    float cmp[4][4];   // Kahan compensation terms
    #pragma unroll
    for (int j = 0; j < 4; j++)
        #pragma unroll
        for (int i = 0; i < 4; i++) { acc[j][i] = 0.f; cmp[j][i] = 0.f; }

    const float* inb = in + (size_t)b * NCH * H * W;

    for (int cb = 0; cb < NCH; cb += CB) {
        __syncthreads();
        // load input tile (with halo, zero-padded)
        #pragma unroll 2
        for (int i = t; i < CB*(TH+2)*(TW+2); i += 256) {
            int ci  = i / ((TH+2)*(TW+2));
            int rem = i - ci*((TH+2)*(TW+2));
            int r   = rem / (TW+2);
            int c   = rem - r*(TW+2);
            int gy  = gy0 + r - 1;
            int gx  = gx0 + c - 1;
            float v = 0.f;
            if ((unsigned)gy < (unsigned)H && (unsigned)gx < (unsigned)W)
                v = inb[((size_t)(cb+ci)*H + gy)*W + gx];
            s_in[ci][r][c] = v;
        }
        // load weight slice: s_w[(ci*9+tap)*WPAD + oc]
        #pragma unroll 4
        for (int i = t; i < OCT*CB*9; i += 256) {
            int oc = i / (CB*9);
            int j  = i - oc*(CB*9);     // j = ci*9 + tap  (global-coalesced per oc)
            float v = 0.f;
            int goc = oc0 + oc;
            if (goc < OC) v = wt[(size_t)goc*(NCH*9) + (size_t)cb*9 + j];
            s_w[j*WPAD + oc] = v;
        }
        __syncthreads();

        #pragma unroll
        for (int ci = 0; ci < CB; ci++) {
            // per-channel 9-tap partials
            float tt[4][4];
            #pragma unroll
            for (int j = 0; j < 4; j++)
                #pragma unroll
                for (int i = 0; i < 4; i++) tt[j][i] = 0.f;

            #pragma unroll
            for (int ky = 0; ky < 3; ky++) {
                const float* irow = &s_in[ci][py+ky][px];
                float i0 = irow[0], i1 = irow[1], i2 = irow[2];
                float i3 = irow[3], i4 = irow[4], i5 = irow[5];
                #pragma unroll
                for (int kx = 0; kx < 3; kx++) {
                    const float4 wv = *(const float4*)&s_w[(ci*9 + ky*3 + kx)*WPAD + (og<<2)];
                    float a0 = (kx==0)?i0:((kx==1)?i1:i2);
                    float a1 = (kx==0)?i1:((kx==1)?i2:i3);
                    float a2 = (kx==0)?i2:((kx==1)?i3:i4);
                    float a3 = (kx==0)?i3:((kx==1)?i4:i5);
                    tt[0][0] += wv.x*a0; tt[0][1] += wv.x*a1; tt[0][2] += wv.x*a2; tt[0][3] += wv.x*a3;
                    tt[1][0] += wv.y*a0; tt[1][1] += wv.y*a1; tt[1][2] += wv.y*a2; tt[1][3] += wv.y*a3;
                    tt[2][0] += wv.z*a0; tt[2][1] += wv.z*a1; tt[2][2] += wv.z*a2; tt[2][3] += wv.z*a3;
                    tt[3][0] += wv.w*a0; tt[3][1] += wv.w*a1; tt[3][2] += wv.w*a2; tt[3][3] += wv.w*a3;
                }
            }
            // Kahan fold of tt into acc
            #pragma unroll
            for (int j = 0; j < 4; j++) {
                #pragma unroll
                for (int i = 0; i < 4; i++) {
                    float y = tt[j][i] - cmp[j][i];
                    float s = acc[j][i] + y;
                    cmp[j][i] = (s - acc[j][i]) - y;
                    acc[j][i] = s;
                }
            }
        }
    }

    int gy = gy0 + py;
    if (gy >= H) return;
    #pragma unroll
    for (int j = 0; j < 4; j++) {
        int goc = oc0 + og*4 + j;
        if (goc >= OC) continue;
        float bv = bias[goc];
        #pragma unroll
        for (int i = 0; i < 4; i++) {
            int gx = gx0 + px + i;
            if (gx >= W) continue;
            float v = (acc[j][i] - cmp[j][i]) + bv;
            if (relu) v = fmaxf(v, 0.f);
            out[((size_t)b*OC + goc)*H*W + (size_t)gy*W + gx] = v;
        }
    }
}

// ---------------------------------------------------------------------------
// cls epilogue: head [B,720,H,W] (channel = a*80 + k) -> scores + class_id.
// argmax/max on logits == argmax/max on sigmoid (monotone); sigmoid at end.
// ---------------------------------------------------------------------------
__global__ void cls_reduce_k(const float* __restrict__ head,
                             float* __restrict__ scores, float* __restrict__ cls_id,
                             int H, int W, int Aoff, int Atot, int total)
{
    int idx = blockIdx.x * blockDim.x + threadIdx.x;
    if (idx >= total) return;
    int HW  = H * W;
    int pos = idx % HW;
    int tmp = idx / HW;
    int a   = tmp % 9;
    int b   = tmp / 9;
    const float* p = head + ((size_t)b*720 + (size_t)a*80) * HW + pos;
    float best = p[0];
    int   bi   = 0;
    #pragma unroll 4
    for (int k = 1; k < 80; k++) {
        float v = p[(size_t)k * HW];
        if (v > best) { best = v; bi = k; }
    }
    size_t o = (size_t)b*Atot + Aoff + (size_t)pos*9 + a;
    scores[o] = 1.f / (1.f + expf(-best));
    cls_id[o] = (float)bi;
}

// ---------------------------------------------------------------------------
// reg epilogue: head [B,36,H,W] (channel = a*4 + j) -> decoded boxes.
// Anchors computed analytically.
// ---------------------------------------------------------------------------
__global__ void reg_decode_k(const float* __restrict__ head, float* __restrict__ boxes,
                             int H, int W, int stride, int Aoff, int Atot, int total)
{
    int idx = blockIdx.x * blockDim.x + threadIdx.x;
    if (idx >= total) return;
    int HW  = H * W;
    int pos = idx % HW;
    int tmp = idx / HW;
    int a   = tmp % 9;
    int b   = tmp / 9;
    int x   = pos % W, y = pos / W;

    const float* p = head + ((size_t)b*36 + (size_t)a*4) * HW + pos;
    float d0 = p[0], d1 = p[HW], d2 = p[2*(size_t)HW], d3 = p[3*(size_t)HW];

    float s     = (float)stride;
    int   ridx  = a / 3, sidx = a - ridx*3;
    float ratio = (ridx == 0) ? 0.5f : ((ridx == 1) ? 1.f : 2.f);
    float scale = (sidx == 0) ? 1.f : ((sidx == 1) ? 1.2599210498948732f : 1.5874010519681994f);
    float w0 = 4.f * s * scale;
    float aw = w0 * rsqrtf(ratio);
    float ah = aw * ratio;
    float cx = (x + 0.5f) * s;
    float cy = (y + 0.5f) * s;

    float pcx = cx + d0 * 0.1f * aw;
    float pcy = cy + d1 * 0.1f * ah;
    float pw  = expf(d2 * 0.2f) * aw;
    float ph  = expf(d3 * 0.2f) * ah;

    float4 out4 = make_float4(pcx - 0.5f*pw, pcy - 0.5f*ph, pcx + 0.5f*pw, pcy + 0.5f*ph);
    size_t o = ((size_t)b*Atot + Aoff + (size_t)pos*9 + a);
    *(float4*)&boxes[o*4] = out4;
}

// ---------------------------------------------------------------------------
extern "C" void kernel_launch(void* const* d_in, const int* in_sizes, int n_in,
                              void* d_out, int out_size)
{
    static const int HS[5] = {64, 32, 16, 8, 4};
    static const int SS[5] = {8, 16, 32, 64, 128};

    const float* feat[5];
    const float *cw[5], *cbv[5], *rw[5], *rbv[5];
    for (int l = 0; l < 5; l++) feat[l] = (const float*)d_in[l];
    for (int i = 0; i < 5; i++) {
        cw[i]  = (const float*)d_in[5  + 2*i];
        cbv[i] = (const float*)d_in[6  + 2*i];
        rw[i]  = (const float*)d_in[15 + 2*i];
        rbv[i] = (const float*)d_in[16 + 2*i];
    }
    int B = in_sizes[0] / (256 * 64 * 64);

    float *buf0, *buf1, *headb;
    cudaGetSymbolAddress((void**)&buf0,  g_buf0);
    cudaGetSymbolAddress((void**)&buf1,  g_buf1);
    cudaGetSymbolAddress((void**)&headb, g_head);
    float* bufs[2] = {buf0, buf1};

    int Aoff[5], Atot = 0;
    for (int l = 0; l < 5; l++) { Aoff[l] = Atot; Atot += HS[l]*HS[l]*9; }

    float* out        = (float*)d_out;
    float* out_scores = out;
    float* out_cls    = out + (size_t)B * Atot;
    float* out_boxes  = out + (size_t)2 * B * Atot;

    for (int l = 0; l < 5; l++) {
        int H = HS[l], W = HS[l];
        int tilesX = (W + TW - 1) / TW;
        int tilesY = (H + TH - 1) / TH;
        dim3 grid(tilesX * tilesY, 4, B);                       // 256 oc / 64
        dim3 gridCls(tilesX * tilesY, (720 + OCT - 1) / OCT, B);
        dim3 gridReg(tilesX * tilesY, 1, B);                    // 36 oc
        int total = B * 9 * H * W;
        int rblk  = (total + 255) / 256;

        // --- cls tower ---
        const float* x = feat[l];
        for (int i = 0; i < 4; i++) {
            conv3x3_k<<<grid, 256>>>(x, cw[i], cbv[i], bufs[i & 1], 256, H, W, tilesX, 1);
            x = bufs[i & 1];
        }
        conv3x3_k<<<gridCls, 256>>>(x, cw[4], cbv[4], headb, 720, H, W, tilesX, 0);
        cls_reduce_k<<<rblk, 256>>>(headb, out_scores, out_cls, H, W, Aoff[l], Atot, total);

        // --- reg tower ---
        x = feat[l];
        for (int i = 0; i < 4; i++) {
            conv3x3_k<<<grid, 256>>>(x, rw[i], rbv[i], bufs[i & 1], 256, H, W, tilesX, 1);
            x = bufs[i & 1];
        }
        conv3x3_k<<<gridReg, 256>>>(x, rw[4], rbv[4], headb, 36, H, W, tilesX, 0);
        reg_decode_k<<<rblk, 256>>>(headb, out_boxes, H, W, SS[l], Aoff[l], Atot, total);
    }
    (void)n_in; (void)out_size;
}

// round 5
// speedup vs baseline: 1.4494x; 1.4474x over previous
#include <cuda_runtime.h>
#include <math.h>

#define NCH 256
#define TW 16
#define TH 4
#define OCT 64
#define CB 16
#define WPAD 68   // padded oc dim for weight smem
#define IRS 20    // padded input row stride (floats) -> 16B-aligned float4 reads

// Scratch (static device globals; allocation is forbidden)
__device__ float g_buf0[8u*256u*64u*64u];   // 33.5 MB
__device__ float g_buf1[8u*256u*64u*64u];   // 33.5 MB
__device__ float g_head[8u*720u*64u*64u];   // 94.4 MB (max head output, level 0 cls)

// ---------------------------------------------------------------------------
// 3x3 SAME conv, C_in = 256 fixed, OC generic, optional ReLU.
// Block: 256 threads computes [64 oc x 64 px] tile (16x4 spatial).
// Thread: 4 oc x 4 px register tile. Smem chunking over input channels (16).
// KAHAN=true (cls tower): 4-channel FMA-chain partials folded into the master
//   accumulator with a compensated step (error ~4e-7; needed because class_id
//   = argmax over 80 logits flips on ~1e-6 ties vs the XLA reference).
// KAHAN=false (reg tower): straight accumulation (boxes tolerate 1e-6 errors).
// ---------------------------------------------------------------------------
template<bool KAHAN>
__global__ __launch_bounds__(256) void conv3x3_k(
    const float* __restrict__ in, const float* __restrict__ wt,
    const float* __restrict__ bias, float* __restrict__ out,
    int OC, int H, int W, int tilesX, int relu)
{
    __shared__ float s_in[CB][TH+2][IRS];
    __shared__ float s_w[CB*9*WPAD];

    const int t   = threadIdx.x;
    const int tX  = blockIdx.x % tilesX;
    const int tY  = blockIdx.x / tilesX;
    const int oc0 = blockIdx.y * OCT;
    const int b   = blockIdx.z;
    const int og  = t & 15;        // oc group: handles oc0 + og*4 .. +3
    const int pg  = t >> 4;        // pixel group: 4 consecutive x at fixed y
    const int px  = (pg & 3) << 2;
    const int py  = pg >> 2;
    const int gx0 = tX * TW, gy0 = tY * TH;

    // weight staging mapping: 4 threads per oc, 9 x LDG.128 each
    const int w_oc = t >> 2;           // 0..63
    const int w_q  = t & 3;            // 0..3
    const int w_goc = oc0 + w_oc;
    const bool w_ok = (w_goc < OC);
    const float* wbase = wt + (size_t)(w_ok ? w_goc : 0) * (NCH*9);

    float acc[4][4];   // master accumulators
    float cmp[4][4];   // Kahan compensation (KAHAN only)
    #pragma unroll
    for (int j = 0; j < 4; j++)
        #pragma unroll
        for (int i = 0; i < 4; i++) { acc[j][i] = 0.f; cmp[j][i] = 0.f; }

    const float* inb = in + (size_t)b * NCH * H * W;

    for (int cb = 0; cb < NCH; cb += CB) {
        __syncthreads();
        // ---- stage input tile (with halo, zero-padded) ----
        #pragma unroll 2
        for (int i = t; i < CB*(TH+2)*(TW+2); i += 256) {
            int ci  = i / ((TH+2)*(TW+2));
            int rem = i - ci*((TH+2)*(TW+2));
            int r   = rem / (TW+2);
            int c   = rem - r*(TW+2);
            int gy  = gy0 + r - 1;
            int gx  = gx0 + c - 1;
            float v = 0.f;
            if ((unsigned)gy < (unsigned)H && (unsigned)gx < (unsigned)W)
                v = inb[((size_t)(cb+ci)*H + gy)*W + gx];
            s_in[ci][r][c] = v;
        }
        // ---- stage weights: s_w[(ci*9+tap)*WPAD + oc], 9x LDG.128/thread ----
        {
            const float* wp = wbase + (size_t)cb*9;
            #pragma unroll
            for (int k = 0; k < 9; k++) {
                int j0 = w_q*4 + k*16;   // covers j = 0..143 across q,k
                float4 wv = make_float4(0.f, 0.f, 0.f, 0.f);
                if (w_ok) wv = *(const float4*)&wp[j0];
                s_w[(j0+0)*WPAD + w_oc] = wv.x;
                s_w[(j0+1)*WPAD + w_oc] = wv.y;
                s_w[(j0+2)*WPAD + w_oc] = wv.z;
                s_w[(j0+3)*WPAD + w_oc] = wv.w;
            }
        }
        __syncthreads();

        if (KAHAN) {
            #pragma unroll 1
            for (int cig = 0; cig < CB; cig += 4) {
                float tt[4][4];
                #pragma unroll
                for (int j = 0; j < 4; j++)
                    #pragma unroll
                    for (int i = 0; i < 4; i++) tt[j][i] = 0.f;

                #pragma unroll
                for (int cc = 0; cc < 4; cc++) {
                    const int ci = cig + cc;
                    #pragma unroll
                    for (int ky = 0; ky < 3; ky++) {
                        const float* irow = &s_in[ci][py+ky][px];
                        const float4 v4 = *(const float4*)irow;
                        float i0 = v4.x, i1 = v4.y, i2 = v4.z, i3 = v4.w;
                        float i4 = irow[4], i5 = irow[5];
                        #pragma unroll
                        for (int kx = 0; kx < 3; kx++) {
                            const float4 wv = *(const float4*)&s_w[(ci*9 + ky*3 + kx)*WPAD + (og<<2)];
                            float a0 = (kx==0)?i0:((kx==1)?i1:i2);
                            float a1 = (kx==0)?i1:((kx==1)?i2:i3);
                            float a2 = (kx==0)?i2:((kx==1)?i3:i4);
                            float a3 = (kx==0)?i3:((kx==1)?i4:i5);
                            tt[0][0] += wv.x*a0; tt[0][1] += wv.x*a1; tt[0][2] += wv.x*a2; tt[0][3] += wv.x*a3;
                            tt[1][0] += wv.y*a0; tt[1][1] += wv.y*a1; tt[1][2] += wv.y*a2; tt[1][3] += wv.y*a3;
                            tt[2][0] += wv.z*a0; tt[2][1] += wv.z*a1; tt[2][2] += wv.z*a2; tt[2][3] += wv.z*a3;
                            tt[3][0] += wv.w*a0; tt[3][1] += wv.w*a1; tt[3][2] += wv.w*a2; tt[3][3] += wv.w*a3;
                        }
                    }
                }
                // compensated fold of the 4-channel partial into acc
                #pragma unroll
                for (int j = 0; j < 4; j++) {
                    #pragma unroll
                    for (int i = 0; i < 4; i++) {
                        float y = tt[j][i] - cmp[j][i];
                        float s = acc[j][i] + y;
                        cmp[j][i] = (s - acc[j][i]) - y;
                        acc[j][i] = s;
                    }
                }
            }
        } else {
            #pragma unroll 4
            for (int ci = 0; ci < CB; ci++) {
                #pragma unroll
                for (int ky = 0; ky < 3; ky++) {
                    const float* irow = &s_in[ci][py+ky][px];
                    const float4 v4 = *(const float4*)irow;
                    float i0 = v4.x, i1 = v4.y, i2 = v4.z, i3 = v4.w;
                    float i4 = irow[4], i5 = irow[5];
                    #pragma unroll
                    for (int kx = 0; kx < 3; kx++) {
                        const float4 wv = *(const float4*)&s_w[(ci*9 + ky*3 + kx)*WPAD + (og<<2)];
                        float a0 = (kx==0)?i0:((kx==1)?i1:i2);
                        float a1 = (kx==0)?i1:((kx==1)?i2:i3);
                        float a2 = (kx==0)?i2:((kx==1)?i3:i4);
                        float a3 = (kx==0)?i3:((kx==1)?i4:i5);
                        acc[0][0] += wv.x*a0; acc[0][1] += wv.x*a1; acc[0][2] += wv.x*a2; acc[0][3] += wv.x*a3;
                        acc[1][0] += wv.y*a0; acc[1][1] += wv.y*a1; acc[1][2] += wv.y*a2; acc[1][3] += wv.y*a3;
                        acc[2][0] += wv.z*a0; acc[2][1] += wv.z*a1; acc[2][2] += wv.z*a2; acc[2][3] += wv.z*a3;
                        acc[3][0] += wv.w*a0; acc[3][1] += wv.w*a1; acc[3][2] += wv.w*a2; acc[3][3] += wv.w*a3;
                    }
                }
            }
        }
    }

    int gy = gy0 + py;
    if (gy >= H) return;
    #pragma unroll
    for (int j = 0; j < 4; j++) {
        int goc = oc0 + og*4 + j;
        if (goc >= OC) continue;
        float bv = bias[goc];
        #pragma unroll
        for (int i = 0; i < 4; i++) {
            int gx = gx0 + px + i;
            if (gx >= W) continue;
            float v = KAHAN ? ((acc[j][i] - cmp[j][i]) + bv) : (acc[j][i] + bv);
            if (relu) v = fmaxf(v, 0.f);
            out[((size_t)b*OC + goc)*H*W + (size_t)gy*W + gx] = v;
        }
    }
}

// ---------------------------------------------------------------------------
// cls epilogue: head [B,720,H,W] (channel = a*80 + k) -> scores + class_id.
// argmax/max on logits == argmax/max on sigmoid (monotone); sigmoid at end.
// ---------------------------------------------------------------------------
__global__ void cls_reduce_k(const float* __restrict__ head,
                             float* __restrict__ scores, float* __restrict__ cls_id,
                             int H, int W, int Aoff, int Atot, int total)
{
    int idx = blockIdx.x * blockDim.x + threadIdx.x;
    if (idx >= total) return;
    int HW  = H * W;
    int pos = idx % HW;
    int tmp = idx / HW;
    int a   = tmp % 9;
    int b   = tmp / 9;
    const float* p = head + ((size_t)b*720 + (size_t)a*80) * HW + pos;
    float best = p[0];
    int   bi   = 0;
    #pragma unroll 4
    for (int k = 1; k < 80; k++) {
        float v = p[(size_t)k * HW];
        if (v > best) { best = v; bi = k; }
    }
    size_t o = (size_t)b*Atot + Aoff + (size_t)pos*9 + a;
    scores[o] = 1.f / (1.f + expf(-best));
    cls_id[o] = (float)bi;
}

// ---------------------------------------------------------------------------
// reg epilogue: head [B,36,H,W] (channel = a*4 + j) -> decoded boxes.
// Anchors computed analytically.
// ---------------------------------------------------------------------------
__global__ void reg_decode_k(const float* __restrict__ head, float* __restrict__ boxes,
                             int H, int W, int stride, int Aoff, int Atot, int total)
{
    int idx = blockIdx.x * blockDim.x + threadIdx.x;
    if (idx >= total) return;
    int HW  = H * W;
    int pos = idx % HW;
    int tmp = idx / HW;
    int a   = tmp % 9;
    int b   = tmp / 9;
    int x   = pos % W, y = pos / W;

    const float* p = head + ((size_t)b*36 + (size_t)a*4) * HW + pos;
    float d0 = p[0], d1 = p[HW], d2 = p[2*(size_t)HW], d3 = p[3*(size_t)HW];

    float s     = (float)stride;
    int   ridx  = a / 3, sidx = a - ridx*3;
    float ratio = (ridx == 0) ? 0.5f : ((ridx == 1) ? 1.f : 2.f);
    float scale = (sidx == 0) ? 1.f : ((sidx == 1) ? 1.2599210498948732f : 1.5874010519681994f);
    float w0 = 4.f * s * scale;
    float aw = w0 * rsqrtf(ratio);
    float ah = aw * ratio;
    float cx = (x + 0.5f) * s;
    float cy = (y + 0.5f) * s;

    float pcx = cx + d0 * 0.1f * aw;
    float pcy = cy + d1 * 0.1f * ah;
    float pw  = expf(d2 * 0.2f) * aw;
    float ph  = expf(d3 * 0.2f) * ah;

    float4 out4 = make_float4(pcx - 0.5f*pw, pcy - 0.5f*ph, pcx + 0.5f*pw, pcy + 0.5f*ph);
    size_t o = ((size_t)b*Atot + Aoff + (size_t)pos*9 + a);
    *(float4*)&boxes[o*4] = out4;
}

// ---------------------------------------------------------------------------
extern "C" void kernel_launch(void* const* d_in, const int* in_sizes, int n_in,
                              void* d_out, int out_size)
{
    static const int HS[5] = {64, 32, 16, 8, 4};
    static const int SS[5] = {8, 16, 32, 64, 128};

    const float* feat[5];
    const float *cw[5], *cbv[5], *rw[5], *rbv[5];
    for (int l = 0; l < 5; l++) feat[l] = (const float*)d_in[l];
    for (int i = 0; i < 5; i++) {
        cw[i]  = (const float*)d_in[5  + 2*i];
        cbv[i] = (const float*)d_in[6  + 2*i];
        rw[i]  = (const float*)d_in[15 + 2*i];
        rbv[i] = (const float*)d_in[16 + 2*i];
    }
    int B = in_sizes[0] / (256 * 64 * 64);

    float *buf0, *buf1, *headb;
    cudaGetSymbolAddress((void**)&buf0,  g_buf0);
    cudaGetSymbolAddress((void**)&buf1,  g_buf1);
    cudaGetSymbolAddress((void**)&headb, g_head);
    float* bufs[2] = {buf0, buf1};

    int Aoff[5], Atot = 0;
    for (int l = 0; l < 5; l++) { Aoff[l] = Atot; Atot += HS[l]*HS[l]*9; }

    float* out        = (float*)d_out;
    float* out_scores = out;
    float* out_cls    = out + (size_t)B * Atot;
    float* out_boxes  = out + (size_t)2 * B * Atot;

    for (int l = 0; l < 5; l++) {
        int H = HS[l], W = HS[l];
        int tilesX = (W + TW - 1) / TW;
        int tilesY = (H + TH - 1) / TH;
        dim3 grid(tilesX * tilesY, 4, B);                       // 256 oc / 64
        dim3 gridCls(tilesX * tilesY, (720 + OCT - 1) / OCT, B);
        dim3 gridReg(tilesX * tilesY, 1, B);                    // 36 oc
        int total = B * 9 * H * W;
        int rblk  = (total + 255) / 256;

        // --- cls tower (compensated: class_id argmax is tie-sensitive) ---
        const float* x = feat[l];
        for (int i = 0; i < 4; i++) {
            conv3x3_k<true><<<grid, 256>>>(x, cw[i], cbv[i], bufs[i & 1], 256, H, W, tilesX, 1);
            x = bufs[i & 1];
        }
        conv3x3_k<true><<<gridCls, 256>>>(x, cw[4], cbv[4], headb, 720, H, W, tilesX, 0);
        cls_reduce_k<<<rblk, 256>>>(headb, out_scores, out_cls, H, W, Aoff[l], Atot, total);

        // --- reg tower (plain accumulation: boxes are tolerant) ---
        x = feat[l];
        for (int i = 0; i < 4; i++) {
            conv3x3_k<false><<<grid, 256>>>(x, rw[i], rbv[i], bufs[i & 1], 256, H, W, tilesX, 1);
            x = bufs[i & 1];
        }
        conv3x3_k<false><<<gridReg, 256>>>(x, rw[4], rbv[4], headb, 36, H, W, tilesX, 0);
        reg_decode_k<<<rblk, 256>>>(headb, out_boxes, H, W, SS[l], Aoff[l], Atot, total);
    }
    (void)n_in; (void)out_size;
}

// round 6
// speedup vs baseline: 1.4556x; 1.0043x over previous
#include <cuda_runtime.h>
#include <math.h>

#define NCH 256
#define TW 16
#define TH 4
#define OCT 64
#define CB 16
#define WPAD 68   // padded oc dim for weight smem (STS conflict reduction)
#define IRS 20    // padded input row stride (floats): 16B-aligned float4 reads

// Scratch (static device globals; allocation is forbidden)
__device__ float g_buf0[8u*256u*64u*64u];   // 33.5 MB
__device__ float g_buf1[8u*256u*64u*64u];   // 33.5 MB
__device__ float g_head[8u*720u*64u*64u];   // 94.4 MB (max head output, level 0 cls)

// 16 FMAs of one weight float4 against a 4-px input window, into ACC[4][4].
#define FMA16(ACC, WV, A0, A1, A2, A3) \
    ACC[0][0] += (WV).x*(A0); ACC[0][1] += (WV).x*(A1); ACC[0][2] += (WV).x*(A2); ACC[0][3] += (WV).x*(A3); \
    ACC[1][0] += (WV).y*(A0); ACC[1][1] += (WV).y*(A1); ACC[1][2] += (WV).y*(A2); ACC[1][3] += (WV).y*(A3); \
    ACC[2][0] += (WV).z*(A0); ACC[2][1] += (WV).z*(A1); ACC[2][2] += (WV).z*(A2); ACC[2][3] += (WV).z*(A3); \
    ACC[3][0] += (WV).w*(A0); ACC[3][1] += (WV).w*(A1); ACC[3][2] += (WV).w*(A2); ACC[3][3] += (WV).w*(A3)

// One input channel (9 taps) into ACC. Explicit kx unroll: no selects possible.
#define CHANNEL9(ACC, CI) \
    _Pragma("unroll") \
    for (int ky = 0; ky < 3; ky++) { \
        const float* irow = &s_in[CI][py+ky][px]; \
        const float4 va = *(const float4*)irow;       /* i0..i3 */ \
        const float4 vb = *(const float4*)(irow + 4); /* i4..i7 (i6,i7 unused) */ \
        { const float4 wv = *(const float4*)&s_w[((CI)*9 + ky*3 + 0)*WPAD + (og<<2)]; \
          FMA16(ACC, wv, va.x, va.y, va.z, va.w); } \
        { const float4 wv = *(const float4*)&s_w[((CI)*9 + ky*3 + 1)*WPAD + (og<<2)]; \
          FMA16(ACC, wv, va.y, va.z, va.w, vb.x); } \
        { const float4 wv = *(const float4*)&s_w[((CI)*9 + ky*3 + 2)*WPAD + (og<<2)]; \
          FMA16(ACC, wv, va.z, va.w, vb.x, vb.y); } \
    }

// ---------------------------------------------------------------------------
// 3x3 SAME conv, C_in = 256 fixed, OC generic, optional ReLU.
// Block: 256 threads computes [64 oc x 64 px] tile (16x4 spatial).
// Thread: 4 oc x 4 px register tile. Smem chunking over input channels (16).
// KAHAN=true (cls tower): 4-channel FMA-chain partials folded into the master
//   accumulator with a compensated step (class_id argmax flips on ~1e-6 ties).
// KAHAN=false (reg tower): straight accumulation (boxes tolerate 1e-6 errors).
// ---------------------------------------------------------------------------
template<bool KAHAN>
__global__ __launch_bounds__(256) void conv3x3_k(
    const float* __restrict__ in, const float* __restrict__ wt,
    const float* __restrict__ bias, float* __restrict__ out,
    int OC, int H, int W, int tilesX, int relu)
{
    __shared__ float s_in[CB][TH+2][IRS];
    __shared__ float s_w[CB*9*WPAD];

    const int t   = threadIdx.x;
    const int tX  = blockIdx.x % tilesX;
    const int tY  = blockIdx.x / tilesX;
    const int oc0 = blockIdx.y * OCT;
    const int b   = blockIdx.z;
    const int og  = t & 15;        // oc group: handles oc0 + og*4 .. +3
    const int pg  = t >> 4;        // pixel group: 4 consecutive x at fixed y
    const int px  = (pg & 3) << 2;
    const int py  = pg >> 2;
    const int gx0 = tX * TW, gy0 = tY * TH;

    // weight staging mapping: 4 threads per oc, 9 x LDG.128 each
    const int w_oc = t >> 2;           // 0..63
    const int w_q  = t & 3;            // 0..3
    const int w_goc = oc0 + w_oc;
    const bool w_ok = (w_goc < OC);
    const float* wbase = wt + (size_t)(w_ok ? w_goc : 0) * (NCH*9);

    float acc[4][4];   // master accumulators
    float cmp[4][4];   // Kahan compensation (KAHAN only)
    #pragma unroll
    for (int j = 0; j < 4; j++)
        #pragma unroll
        for (int i = 0; i < 4; i++) { acc[j][i] = 0.f; cmp[j][i] = 0.f; }

    const float* inb = in + (size_t)b * NCH * H * W;

    for (int cb = 0; cb < NCH; cb += CB) {
        __syncthreads();
        // ---- stage input tile (with halo, zero-padded) ----
        #pragma unroll 2
        for (int i = t; i < CB*(TH+2)*(TW+2); i += 256) {
            int ci  = i / ((TH+2)*(TW+2));
            int rem = i - ci*((TH+2)*(TW+2));
            int r   = rem / (TW+2);
            int c   = rem - r*(TW+2);
            int gy  = gy0 + r - 1;
            int gx  = gx0 + c - 1;
            float v = 0.f;
            if ((unsigned)gy < (unsigned)H && (unsigned)gx < (unsigned)W)
                v = inb[((size_t)(cb+ci)*H + gy)*W + gx];
            s_in[ci][r][c] = v;
        }
        // ---- stage weights: s_w[(ci*9+tap)*WPAD + oc], 9x LDG.128/thread ----
        {
            const float* wp = wbase + (size_t)cb*9;
            #pragma unroll
            for (int k = 0; k < 9; k++) {
                int j0 = w_q*4 + k*16;   // covers j = 0..143 across q,k
                float4 wv = make_float4(0.f, 0.f, 0.f, 0.f);
                if (w_ok) wv = *(const float4*)&wp[j0];
                s_w[(j0+0)*WPAD + w_oc] = wv.x;
                s_w[(j0+1)*WPAD + w_oc] = wv.y;
                s_w[(j0+2)*WPAD + w_oc] = wv.z;
                s_w[(j0+3)*WPAD + w_oc] = wv.w;
            }
        }
        __syncthreads();

        if (KAHAN) {
            #pragma unroll 1
            for (int cig = 0; cig < CB; cig += 4) {
                float tt[4][4];
                #pragma unroll
                for (int j = 0; j < 4; j++)
                    #pragma unroll
                    for (int i = 0; i < 4; i++) tt[j][i] = 0.f;

                #pragma unroll
                for (int cc = 0; cc < 4; cc++) {
                    const int ci = cig + cc;
                    CHANNEL9(tt, ci)
                }
                // compensated fold of the 4-channel partial into acc
                #pragma unroll
                for (int j = 0; j < 4; j++) {
                    #pragma unroll
                    for (int i = 0; i < 4; i++) {
                        float y = tt[j][i] - cmp[j][i];
                        float s = acc[j][i] + y;
                        cmp[j][i] = (s - acc[j][i]) - y;
                        acc[j][i] = s;
                    }
                }
            }
        } else {
            #pragma unroll 4
            for (int ci = 0; ci < CB; ci++) {
                CHANNEL9(acc, ci)
            }
        }
    }

    int gy = gy0 + py;
    if (gy >= H) return;
    #pragma unroll
    for (int j = 0; j < 4; j++) {
        int goc = oc0 + og*4 + j;
        if (goc >= OC) continue;
        float bv = bias[goc];
        #pragma unroll
        for (int i = 0; i < 4; i++) {
            int gx = gx0 + px + i;
            if (gx >= W) continue;
            float v = KAHAN ? ((acc[j][i] - cmp[j][i]) + bv) : (acc[j][i] + bv);
            if (relu) v = fmaxf(v, 0.f);
            out[((size_t)b*OC + goc)*H*W + (size_t)gy*W + gx] = v;
        }
    }
}

// ---------------------------------------------------------------------------
// cls epilogue: head [B,720,H,W] (channel = a*80 + k) -> scores + class_id.
// argmax/max on logits == argmax/max on sigmoid (monotone); sigmoid at end.
// ---------------------------------------------------------------------------
__global__ void cls_reduce_k(const float* __restrict__ head,
                             float* __restrict__ scores, float* __restrict__ cls_id,
                             int H, int W, int Aoff, int Atot, int total)
{
    int idx = blockIdx.x * blockDim.x + threadIdx.x;
    if (idx >= total) return;
    int HW  = H * W;
    int pos = idx % HW;
    int tmp = idx / HW;
    int a   = tmp % 9;
    int b   = tmp / 9;
    const float* p = head + ((size_t)b*720 + (size_t)a*80) * HW + pos;
    float best = p[0];
    int   bi   = 0;
    #pragma unroll 4
    for (int k = 1; k < 80; k++) {
        float v = p[(size_t)k * HW];
        if (v > best) { best = v; bi = k; }
    }
    size_t o = (size_t)b*Atot + Aoff + (size_t)pos*9 + a;
    scores[o] = 1.f / (1.f + expf(-best));
    cls_id[o] = (float)bi;
}

// ---------------------------------------------------------------------------
// reg epilogue: head [B,36,H,W] (channel = a*4 + j) -> decoded boxes.
// Anchors computed analytically.
// ---------------------------------------------------------------------------
__global__ void reg_decode_k(const float* __restrict__ head, float* __restrict__ boxes,
                             int H, int W, int stride, int Aoff, int Atot, int total)
{
    int idx = blockIdx.x * blockDim.x + threadIdx.x;
    if (idx >= total) return;
    int HW  = H * W;
    int pos = idx % HW;
    int tmp = idx / HW;
    int a   = tmp % 9;
    int b   = tmp / 9;
    int x   = pos % W, y = pos / W;

    const float* p = head + ((size_t)b*36 + (size_t)a*4) * HW + pos;
    float d0 = p[0], d1 = p[HW], d2 = p[2*(size_t)HW], d3 = p[3*(size_t)HW];

    float s     = (float)stride;
    int   ridx  = a / 3, sidx = a - ridx*3;
    float ratio = (ridx == 0) ? 0.5f : ((ridx == 1) ? 1.f : 2.f);
    float scale = (sidx == 0) ? 1.f : ((sidx == 1) ? 1.2599210498948732f : 1.5874010519681994f);
    float w0 = 4.f * s * scale;
    float aw = w0 * rsqrtf(ratio);
    float ah = aw * ratio;
    float cx = (x + 0.5f) * s;
    float cy = (y + 0.5f) * s;

    float pcx = cx + d0 * 0.1f * aw;
    float pcy = cy + d1 * 0.1f * ah;
    float pw  = expf(d2 * 0.2f) * aw;
    float ph  = expf(d3 * 0.2f) * ah;

    float4 out4 = make_float4(pcx - 0.5f*pw, pcy - 0.5f*ph, pcx + 0.5f*pw, pcy + 0.5f*ph);
    size_t o = ((size_t)b*Atot + Aoff + (size_t)pos*9 + a);
    *(float4*)&boxes[o*4] = out4;
}

// ---------------------------------------------------------------------------
extern "C" void kernel_launch(void* const* d_in, const int* in_sizes, int n_in,
                              void* d_out, int out_size)
{
    static const int HS[5] = {64, 32, 16, 8, 4};
    static const int SS[5] = {8, 16, 32, 64, 128};

    const float* feat[5];
    const float *cw[5], *cbv[5], *rw[5], *rbv[5];
    for (int l = 0; l < 5; l++) feat[l] = (const float*)d_in[l];
    for (int i = 0; i < 5; i++) {
        cw[i]  = (const float*)d_in[5  + 2*i];
        cbv[i] = (const float*)d_in[6  + 2*i];
        rw[i]  = (const float*)d_in[15 + 2*i];
        rbv[i] = (const float*)d_in[16 + 2*i];
    }
    int B = in_sizes[0] / (256 * 64 * 64);

    float *buf0, *buf1, *headb;
    cudaGetSymbolAddress((void**)&buf0,  g_buf0);
    cudaGetSymbolAddress((void**)&buf1,  g_buf1);
    cudaGetSymbolAddress((void**)&headb, g_head);
    float* bufs[2] = {buf0, buf1};

    int Aoff[5], Atot = 0;
    for (int l = 0; l < 5; l++) { Aoff[l] = Atot; Atot += HS[l]*HS[l]*9; }

    float* out        = (float*)d_out;
    float* out_scores = out;
    float* out_cls    = out + (size_t)B * Atot;
    float* out_boxes  = out + (size_t)2 * B * Atot;

    for (int l = 0; l < 5; l++) {
        int H = HS[l], W = HS[l];
        int tilesX = (W + TW - 1) / TW;
        int tilesY = (H + TH - 1) / TH;
        dim3 grid(tilesX * tilesY, 4, B);                       // 256 oc / 64
        dim3 gridCls(tilesX * tilesY, (720 + OCT - 1) / OCT, B);
        dim3 gridReg(tilesX * tilesY, 1, B);                    // 36 oc
        int total = B * 9 * H * W;
        int rblk  = (total + 255) / 256;

        // --- cls tower (compensated: class_id argmax is tie-sensitive) ---
        const float* x = feat[l];
        for (int i = 0; i < 4; i++) {
            conv3x3_k<true><<<grid, 256>>>(x, cw[i], cbv[i], bufs[i & 1], 256, H, W, tilesX, 1);
            x = bufs[i & 1];
        }
        conv3x3_k<true><<<gridCls, 256>>>(x, cw[4], cbv[4], headb, 720, H, W, tilesX, 0);
        cls_reduce_k<<<rblk, 256>>>(headb, out_scores, out_cls, H, W, Aoff[l], Atot, total);

        // --- reg tower (plain accumulation: boxes are tolerant) ---
        x = feat[l];
        for (int i = 0; i < 4; i++) {
            conv3x3_k<false><<<grid, 256>>>(x, rw[i], rbv[i], bufs[i & 1], 256, H, W, tilesX, 1);
            x = bufs[i & 1];
        }
        conv3x3_k<false><<<gridReg, 256>>>(x, rw[4], rbv[4], headb, 36, H, W, tilesX, 0);
        reg_decode_k<<<rblk, 256>>>(headb, out_boxes, H, W, SS[l], Aoff[l], Atot, total);
    }
    (void)n_in; (void)out_size;
}